// round 2
// baseline (speedup 1.0000x reference)
#include <cuda_runtime.h>
#include <math.h>

// ---------------- problem constants ----------------
#define Bn   16
#define NP   1296
#define DIM  768
#define Cc   201
#define Kp   5
#define DA   64
#define Nn   (Bn*NP)          // 20736
#define CK   (Cc*Kp)          // 1005

// output layout (tuple order, flattened, float32)
#define OFF_CLASS  ((size_t)0)
#define LEN_CLASS  ((size_t)Bn*(Cc-1))                 // 3200
#define OFF_L      (OFF_CLASS + LEN_CLASS)             // 3200
#define LEN_L      ((size_t)Nn*CK)                     // 20839680
#define OFF_IMG    (OFF_L + LEN_L)                     // 20842880
#define LEN_IMG    ((size_t)Bn*CK)                     // 16080
#define OFF_PART   (OFF_IMG + LEN_IMG)                 // 20858960
#define LEN_PART   ((size_t)Nn)                        // 20736
#define OFF_PSEUDO (OFF_PART + LEN_PART)               // 20879696
#define LEN_PSEUDO ((size_t)Nn)                        // 20736
#define OFF_PNEW   (OFF_PSEUDO + LEN_PSEUDO)           // 20900432

// ---------------- scratch (static device globals; no allocation) ----------------
__device__ float g_proto_ad[CK*DA];     // [1005,64]
__device__ float g_feat_ad[(size_t)Nn*DA]; // [20736,64]
__device__ int   g_labels_flat[Nn];
__device__ int   g_counts[256];
__device__ float g_Qn[(size_t)Nn*Kp];
__device__ float g_Pcand[(size_t)CK*DIM];

// ---------------- zero scratch + image_logits region ----------------
__global__ void zero_kernel(float* img) {
    int i = blockIdx.x*256 + threadIdx.x;
    if (i < CK*DIM) g_Pcand[i] = 0.f;
    if (i < 256)    g_counts[i] = 0;
    if (i < Bn*CK)  img[i] = 0.f;
}

// ---------------- proto_ad = l2norm(sigmoid(prototypes @ wp + bp)) ----------------
__global__ __launch_bounds__(64) void proto_kernel(const float* __restrict__ proto,
                                                   const float* __restrict__ wp,
                                                   const float* __restrict__ bp) {
    __shared__ float row[DIM];
    __shared__ float red[64];
    int r = blockIdx.x;   // 0..1004
    int t = threadIdx.x;  // 0..63
    for (int d = t; d < DIM; d += 64) row[d] = proto[(size_t)r*DIM + d];
    __syncthreads();
    float s = bp[t];
    #pragma unroll 4
    for (int d = 0; d < DIM; d++) s += row[d]*wp[(size_t)d*DA + t];
    float v = 1.f/(1.f + expf(-s));
    red[t] = v*v;
    __syncthreads();
    for (int off = 32; off > 0; off >>= 1) {
        if (t < off) red[t] += red[t+off];
        __syncthreads();
    }
    float denom = fmaxf(sqrtf(red[0]), 1e-12f);
    g_proto_ad[(size_t)r*DA + t] = v/denom;
}

// ---------------- feat_ad = sigmoid(patch_tokens @ wf + bf) ----------------
__global__ __launch_bounds__(256) void feat_gemm(const float* __restrict__ A,
                                                 const float* __restrict__ W,
                                                 const float* __restrict__ bias) {
    __shared__ float As[64][65];
    __shared__ float Bs[64][68];
    int m0 = blockIdx.x*64;
    int t = threadIdx.x;
    int tx = t & 15, ty = t >> 4;
    float acc[4][4] = {};
    for (int kc = 0; kc < DIM; kc += 64) {
        __syncthreads();
        #pragma unroll
        for (int i = 0; i < 16; i++) {
            int e = i*256 + t;
            int m = e >> 6, kk = e & 63;
            As[m][kk] = A[(size_t)(m0+m)*DIM + kc + kk];
        }
        #pragma unroll
        for (int i = 0; i < 16; i++) {
            int e = i*256 + t;
            int kk = e >> 6, cc = e & 63;
            Bs[kk][cc] = W[(size_t)(kc+kk)*DA + cc];
        }
        __syncthreads();
        #pragma unroll
        for (int kk = 0; kk < 64; kk++) {
            float a[4];
            #pragma unroll
            for (int i = 0; i < 4; i++) a[i] = As[ty*4+i][kk];
            float4 bv = *(const float4*)&Bs[kk][tx*4];
            float bb[4] = {bv.x, bv.y, bv.z, bv.w};
            #pragma unroll
            for (int i = 0; i < 4; i++)
                #pragma unroll
                for (int j = 0; j < 4; j++) acc[i][j] += a[i]*bb[j];
        }
    }
    #pragma unroll
    for (int i = 0; i < 4; i++) {
        int m = m0 + ty*4 + i;
        #pragma unroll
        for (int j = 0; j < 4; j++) {
            int cdx = tx*4 + j;
            float v = acc[i][j] + bias[cdx];
            g_feat_ad[(size_t)m*DA + cdx] = 1.f/(1.f + expf(-v));
        }
    }
}

// ---------------- L = feat_ad @ proto_ad^T ----------------
__global__ __launch_bounds__(256) void l_gemm(float* __restrict__ Lout) {
    __shared__ float As[64][65];
    __shared__ float Bs[64][68];
    int m0 = blockIdx.x*64, n0 = blockIdx.y*64;
    int t = threadIdx.x, tx = t & 15, ty = t >> 4;
    #pragma unroll
    for (int i = 0; i < 16; i++) {
        int e = i*256 + t;
        int m = e >> 6, kk = e & 63;
        As[m][kk] = g_feat_ad[(size_t)(m0+m)*DA + kk];
    }
    #pragma unroll
    for (int i = 0; i < 16; i++) {
        int e = i*256 + t;
        int n = e >> 6, kk = e & 63;
        Bs[kk][n] = (n0+n < CK) ? g_proto_ad[(size_t)(n0+n)*DA + kk] : 0.f;
    }
    __syncthreads();
    float acc[4][4] = {};
    #pragma unroll
    for (int kk = 0; kk < 64; kk++) {
        float a[4];
        #pragma unroll
        for (int i = 0; i < 4; i++) a[i] = As[ty*4+i][kk];
        float4 bv = *(const float4*)&Bs[kk][tx*4];
        float bb[4] = {bv.x, bv.y, bv.z, bv.w};
        #pragma unroll
        for (int i = 0; i < 4; i++)
            #pragma unroll
            for (int j = 0; j < 4; j++) acc[i][j] += a[i]*bb[j];
    }
    #pragma unroll
    for (int i = 0; i < 4; i++) {
        size_t m = (size_t)(m0 + ty*4 + i);
        #pragma unroll
        for (int j = 0; j < 4; j++) {
            int n = n0 + tx*4 + j;
            if (n < CK) Lout[m*CK + n] = acc[i][j];
        }
    }
}

// ---------------- image_logits = max over NP (L >= 0, int-bits atomicMax valid) ----------------
__global__ __launch_bounds__(1024) void imgmax_kernel(const float* __restrict__ L,
                                                      float* __restrict__ img) {
    int b = blockIdx.x;   // 0..15
    int j = blockIdx.y;   // 0..15 (n chunk of 81)
    int ck = threadIdx.x;
    if (ck >= CK) return;
    const float* base = L + ((size_t)b*NP + (size_t)j*81)*CK + ck;
    float m = 0.f;
    #pragma unroll 3
    for (int n = 0; n < 81; n++) m = fmaxf(m, base[(size_t)n*CK]);
    atomicMax((int*)&img[(size_t)b*CK + ck], __float_as_int(m));
}

// ---------------- class_logits = sum_k img[:, :-1, :] * (softmax(sa)*K) ----------------
__global__ __launch_bounds__(256) void classlog_kernel(const float* __restrict__ img,
                                                       const float* __restrict__ sa,
                                                       float* __restrict__ out) {
    int b = blockIdx.x;
    int c = threadIdx.x;
    if (c >= Cc-1) return;
    float s[Kp]; float mx = -INFINITY;
    #pragma unroll
    for (int k = 0; k < Kp; k++) { s[k] = sa[c*Kp + k]; mx = fmaxf(mx, s[k]); }
    float e[Kp]; float tot = 0.f;
    #pragma unroll
    for (int k = 0; k < Kp; k++) { e[k] = expf(s[k]-mx); tot += e[k]; }
    float acc = 0.f;
    #pragma unroll
    for (int k = 0; k < Kp; k++) {
        float w = e[k]/tot*(float)Kp;
        acc += img[(size_t)b*CK + c*Kp + k]*w;
    }
    out[(size_t)b*(Cc-1) + c] = acc;
}

// ---------------- pseudo labels (fg/bg decision) + counts ----------------
__global__ __launch_bounds__(256) void pseudo_kernel(const float* __restrict__ L,
                                                     const int* __restrict__ labels,
                                                     float* __restrict__ out_pl) {
    __shared__ float fg[NP], bg[NP];
    __shared__ float red[256];
    int b = blockIdx.x, t = threadIdx.x;
    int lab = labels[b];
    for (int n = t; n < NP; n += 256) {
        const float* p = L + ((size_t)b*NP + n)*CK;
        float f = 0.f, g = 0.f;
        #pragma unroll
        for (int k = 0; k < Kp; k++) { f += p[lab*Kp + k]; g += p[(Cc-1)*Kp + k]; }
        fg[n] = f; bg[n] = g;
    }
    __syncthreads();
    float sf = 0.f, sb = 0.f;
    for (int n = t; n < NP; n += 256) { sf += fabsf(fg[n]); sb += fabsf(bg[n]); }
    red[t] = sf; __syncthreads();
    for (int off = 128; off > 0; off >>= 1) { if (t < off) red[t] += red[t+off]; __syncthreads(); }
    float Sf = fmaxf(red[0], 1e-12f); __syncthreads();
    red[t] = sb; __syncthreads();
    for (int off = 128; off > 0; off >>= 1) { if (t < off) red[t] += red[t+off]; __syncthreads(); }
    float Sb = fmaxf(red[0], 1e-12f); __syncthreads();
    for (int n = t; n < NP; n += 256) {
        bool m = (fg[n]/Sf) > (bg[n]/Sb);
        int pl = m ? lab : (Cc-1);
        out_pl[(size_t)b*NP + n] = (float)pl;
        g_labels_flat[b*NP + n] = pl;
        atomicAdd(&g_counts[pl], 1);
    }
}

// ---------------- masked sinkhorn per class (block per class) ----------------
__global__ __launch_bounds__(512) void sinkhorn_kernel(const float* __restrict__ L) {
    int c = blockIdx.x, t = threadIdx.x;
    int n_c = g_counts[c];
    if (n_c == 0) return;
    __shared__ float red[512];
    __shared__ float bc[8];

    // pass 1: lmax over masked entries
    float lm = -INFINITY;
    for (int n = t; n < Nn; n += 512) {
        if (g_labels_flat[n] == c) {
            const float* p = L + (size_t)n*CK + c*Kp;
            #pragma unroll
            for (int k = 0; k < Kp; k++) lm = fmaxf(lm, p[k]);
        }
    }
    red[t] = lm; __syncthreads();
    for (int off = 256; off > 0; off >>= 1) { if (t < off) red[t] = fmaxf(red[t], red[t+off]); __syncthreads(); }
    float lmax = red[0]; __syncthreads();

    // pass 2: exp + total
    float tot = 0.f;
    for (int n = t; n < Nn; n += 512) {
        if (g_labels_flat[n] == c) {
            const float* p = L + (size_t)n*CK + c*Kp;
            float* q = g_Qn + (size_t)n*Kp;
            #pragma unroll
            for (int k = 0; k < Kp; k++) { float e = expf((p[k]-lmax)/0.05f); q[k] = e; tot += e; }
        }
    }
    red[t] = tot; __syncthreads();
    for (int off = 256; off > 0; off >>= 1) { if (t < off) red[t] += red[t+off]; __syncthreads(); }
    float T = fmaxf(red[0], 1e-12f); __syncthreads();

    // pass 3: Q /= T
    for (int n = t; n < Nn; n += 512)
        if (g_labels_flat[n] == c) {
            float* q = g_Qn + (size_t)n*Kp;
            #pragma unroll
            for (int k = 0; k < Kp; k++) q[k] = q[k]/T;
        }
    __syncthreads();

    float ncf = fmaxf((float)n_c, 1.0f);
    for (int it = 0; it < 3; it++) {
        // column sums
        float cs[Kp] = {0,0,0,0,0};
        for (int n = t; n < Nn; n += 512)
            if (g_labels_flat[n] == c) {
                float* q = g_Qn + (size_t)n*Kp;
                #pragma unroll
                for (int k = 0; k < Kp; k++) cs[k] += q[k];
            }
        #pragma unroll
        for (int k = 0; k < Kp; k++) {
            red[t] = cs[k]; __syncthreads();
            for (int off = 256; off > 0; off >>= 1) { if (t < off) red[t] += red[t+off]; __syncthreads(); }
            if (t == 0) bc[k] = fmaxf(red[0], 1e-12f);
            __syncthreads();
        }
        float csm[Kp];
        #pragma unroll
        for (int k = 0; k < Kp; k++) csm[k] = bc[k];
        // apply col norm, then row norm (final iteration folds * n_c)
        for (int n = t; n < Nn; n += 512)
            if (g_labels_flat[n] == c) {
                float* q = g_Qn + (size_t)n*Kp;
                float qq[Kp]; float rs = 0.f;
                #pragma unroll
                for (int k = 0; k < Kp; k++) { qq[k] = q[k]/csm[k]/5.0f; rs += qq[k]; }
                rs = fmaxf(rs, 1e-12f);
                #pragma unroll
                for (int k = 0; k < Kp; k++) {
                    float v = qq[k]/rs/ncf;
                    if (it == 2) v *= ncf;   // Q * n_c (reference does this after the loop)
                    q[k] = v;
                }
            }
        __syncthreads();
    }
}

// ---------------- part assignment maps ----------------
__global__ __launch_bounds__(256) void part_kernel(float* __restrict__ out) {
    int n = blockIdx.x*256 + threadIdx.x;
    if (n >= Nn) return;
    const float* q = g_Qn + (size_t)n*Kp;
    int bi = 0; float best = q[0];
    #pragma unroll
    for (int k = 1; k < Kp; k++) if (q[k] > best) { best = q[k]; bi = k; }
    out[n] = (float)(bi + g_labels_flat[n]*Kp);
}

// ---------------- P_cand = sum_n Q[c,n,k] * l2norm(patch)[n,d] ----------------
__global__ __launch_bounds__(256) void pcand_kernel(const float* __restrict__ patches,
                                                    const int* __restrict__ labels) {
    __shared__ float red[8];
    __shared__ float s_inv;
    int b = blockIdx.x, j = blockIdx.y, t = threadIdx.x;
    int labfg = labels[b];
    float accF[Kp][3] = {}, accB[Kp][3] = {};
    int n0 = b*NP + j*162;
    for (int p = 0; p < 162; p++) {
        int n = n0 + p;
        const float* x = patches + (size_t)n*DIM;
        float v0 = x[t], v1 = x[t+256], v2 = x[t+512];
        float ss = v0*v0 + v1*v1 + v2*v2;
        #pragma unroll
        for (int o = 16; o > 0; o >>= 1) ss += __shfl_xor_sync(0xffffffffu, ss, o);
        if ((t & 31) == 0) red[t >> 5] = ss;
        __syncthreads();
        if (t < 8) {
            float w = red[t];
            #pragma unroll
            for (int o = 4; o > 0; o >>= 1) w += __shfl_xor_sync(0xffu, w, o);
            if (t == 0) s_inv = 1.0f/fmaxf(sqrtf(w), 1e-12f);
        }
        __syncthreads();
        float inv = s_inv;
        __syncthreads();   // protect red/s_inv reuse next patch
        v0 *= inv; v1 *= inv; v2 *= inv;
        int lab = g_labels_flat[n];
        const float* q = g_Qn + (size_t)n*Kp;
        if (lab == Cc-1) {
            #pragma unroll
            for (int k = 0; k < Kp; k++) { float qk = q[k]; accB[k][0] += qk*v0; accB[k][1] += qk*v1; accB[k][2] += qk*v2; }
        } else {
            #pragma unroll
            for (int k = 0; k < Kp; k++) { float qk = q[k]; accF[k][0] += qk*v0; accF[k][1] += qk*v1; accF[k][2] += qk*v2; }
        }
    }
    #pragma unroll
    for (int k = 0; k < Kp; k++) {
        float* pf = g_Pcand + ((size_t)labfg*Kp + k)*DIM;
        float* pb = g_Pcand + ((size_t)(Cc-1)*Kp + k)*DIM;
        atomicAdd(&pf[t],     accF[k][0]);
        atomicAdd(&pf[t+256], accF[k][1]);
        atomicAdd(&pf[t+512], accF[k][2]);
        atomicAdd(&pb[t],     accB[k][0]);
        atomicAdd(&pb[t+256], accB[k][1]);
        atomicAdd(&pb[t+512], accB[k][2]);
    }
}

// ---------------- P_new = present ? gamma*P + (1-gamma)*P_cand : P ----------------
__global__ __launch_bounds__(256) void pnew_kernel(const float* __restrict__ proto,
                                                   float* __restrict__ out) {
    int ck = blockIdx.x, t = threadIdx.x;
    int c = ck/Kp;
    bool present = (g_counts[c] > 0);
    for (int d = t; d < DIM; d += 256) {
        size_t idx = (size_t)ck*DIM + d;
        float p = proto[idx];
        out[idx] = present ? (0.999f*p + 0.001f*g_Pcand[idx]) : p;
    }
}

// ---------------- launch ----------------
extern "C" void kernel_launch(void* const* d_in, const int* in_sizes, int n_in,
                              void* d_out, int out_size) {
    const float* patch  = (const float*)d_in[0];
    const float* proto  = (const float*)d_in[1];
    const float* sa     = (const float*)d_in[2];
    const float* wf     = (const float*)d_in[3];
    const float* bf     = (const float*)d_in[4];
    const float* wp     = (const float*)d_in[5];
    const float* bp     = (const float*)d_in[6];
    const int*   labels = (const int*)d_in[7];
    float* out  = (float*)d_out;
    float* Lout = out + OFF_L;
    float* img  = out + OFF_IMG;

    zero_kernel<<<(CK*DIM + 255)/256, 256>>>(img);
    proto_kernel<<<CK, 64>>>(proto, wp, bp);
    feat_gemm<<<Nn/64, 256>>>(patch, wf, bf);
    l_gemm<<<dim3(Nn/64, (CK+63)/64), 256>>>(Lout);
    imgmax_kernel<<<dim3(Bn, 16), 1024>>>(Lout, img);
    classlog_kernel<<<Bn, 256>>>(img, sa, out + OFF_CLASS);
    pseudo_kernel<<<Bn, 256>>>(Lout, labels, out + OFF_PSEUDO);
    sinkhorn_kernel<<<Cc, 512>>>(Lout);
    part_kernel<<<(Nn + 255)/256, 256>>>(out + OFF_PART);
    pcand_kernel<<<dim3(Bn, 8), 256>>>(patch, labels);
    pnew_kernel<<<CK, 256>>>(proto, out + OFF_PNEW);
}

// round 4
// speedup vs baseline: 1.1505x; 1.1505x over previous
#include <cuda_runtime.h>
#include <math.h>

// ---------------- problem constants ----------------
#define Bn   16
#define NP   1296
#define DIM  768
#define Cc   201
#define Kp   5
#define DA   64
#define Nn   (Bn*NP)          // 20736
#define CK   (Cc*Kp)          // 1005

// output layout (tuple order, flattened, float32)
#define OFF_CLASS  ((size_t)0)
#define LEN_CLASS  ((size_t)Bn*(Cc-1))                 // 3200
#define OFF_L      (OFF_CLASS + LEN_CLASS)             // 3200
#define LEN_L      ((size_t)Nn*CK)                     // 20839680
#define OFF_IMG    (OFF_L + LEN_L)                     // 20842880
#define LEN_IMG    ((size_t)Bn*CK)                     // 16080
#define OFF_PART   (OFF_IMG + LEN_IMG)
#define LEN_PART   ((size_t)Nn)
#define OFF_PSEUDO (OFF_PART + LEN_PART)
#define LEN_PSEUDO ((size_t)Nn)
#define OFF_PNEW   (OFF_PSEUDO + LEN_PSEUDO)

// packed f32x2 helpers
#define FMA2(d,a,b,c) asm("fma.rn.f32x2 %0, %1, %2, %3;" : "=l"(d) : "l"(a), "l"(b), "l"(c))
#define PACK2(d,lo,hi) asm("mov.b64 %0, {%1, %2};" : "=l"(d) : "r"(__float_as_uint(lo)), "r"(__float_as_uint(hi)))

// ---------------- scratch (static device globals; no allocation) ----------------
__device__ float g_proto_ad[CK*DA];        // [1005,64]
__device__ float g_feat_ad[(size_t)Nn*DA]; // [20736,64]
__device__ float g_invn[Nn];
__device__ int   g_labels_flat[Nn];
__device__ int   g_counts[256];
__device__ float g_Qn[(size_t)Nn*Kp];
__device__ float g_Pcand[(size_t)CK*DIM];

// ---------------- zero scratch + image_logits region ----------------
__global__ void zero_kernel(float* img) {
    int i = blockIdx.x*256 + threadIdx.x;
    if (i < CK*DIM) g_Pcand[i] = 0.f;
    if (i < 256)    g_counts[i] = 0;
    if (i < Bn*CK)  img[i] = 0.f;
}

// ---------------- proto_ad = l2norm(sigmoid(prototypes @ wp + bp)) ----------------
__global__ __launch_bounds__(64) void proto_kernel(const float* __restrict__ proto,
                                                   const float* __restrict__ wp,
                                                   const float* __restrict__ bp) {
    __shared__ float4 rowv[DIM/4];
    __shared__ float red[64];
    int r = blockIdx.x;   // 0..1004
    int t = threadIdx.x;  // 0..63
    const float4* src = (const float4*)(proto + (size_t)r*DIM);
    #pragma unroll
    for (int j = 0; j < 3; j++) rowv[t + 64*j] = src[t + 64*j];
    __syncthreads();
    float s0 = bp[t], s1 = 0.f, s2 = 0.f, s3 = 0.f;
    #pragma unroll 4
    for (int d4 = 0; d4 < DIM/4; d4++) {
        float4 rv = rowv[d4];
        int d = d4*4;
        s0 += rv.x*wp[(size_t)d*DA + t];
        s1 += rv.y*wp[(size_t)(d+1)*DA + t];
        s2 += rv.z*wp[(size_t)(d+2)*DA + t];
        s3 += rv.w*wp[(size_t)(d+3)*DA + t];
    }
    float v = 1.f/(1.f + expf(-((s0+s1)+(s2+s3))));
    red[t] = v*v;
    __syncthreads();
    for (int off = 32; off > 0; off >>= 1) {
        if (t < off) red[t] += red[t+off];
        __syncthreads();
    }
    float denom = fmaxf(sqrtf(red[0]), 1e-12f);
    g_proto_ad[(size_t)r*DA + t] = v/denom;
}

// ---------------- inv L2 norm of each patch (warp per patch) ----------------
__global__ __launch_bounds__(256) void norm_kernel(const float* __restrict__ patches) {
    int w = (blockIdx.x*256 + threadIdx.x) >> 5;  // patch index
    int lane = threadIdx.x & 31;
    if (w >= Nn) return;
    const float4* p = (const float4*)(patches + (size_t)w*DIM);
    float s = 0.f;
    #pragma unroll
    for (int j = 0; j < 6; j++) {
        float4 v = p[lane + 32*j];
        s += v.x*v.x + v.y*v.y + v.z*v.z + v.w*v.w;
    }
    #pragma unroll
    for (int o = 16; o > 0; o >>= 1) s += __shfl_xor_sync(0xffffffffu, s, o);
    if (lane == 0) g_invn[w] = 1.0f/fmaxf(sqrtf(s), 1e-12f);
}

// ---------------- feat_ad = sigmoid(patch_tokens @ wf + bf)  (96x64 tile, f32x2) -------
__global__ __launch_bounds__(256) void feat_gemm(const float* __restrict__ A,
                                                 const float* __restrict__ W,
                                                 const float* __restrict__ bias) {
    __shared__ __align__(16) unsigned long long As2[48*64];   // (rowpair, k) packed
    __shared__ float Bs[64][68];                               // (k, c)
    float* As2f = (float*)As2;
    int m0 = blockIdx.x*96;
    int t = threadIdx.x;
    int tx = t & 15, ty = t >> 4;
    unsigned long long acc2[3][4];
    #pragma unroll
    for (int i = 0; i < 3; i++)
        #pragma unroll
        for (int j = 0; j < 4; j++) acc2[i][j] = 0ull;

    for (int kc = 0; kc < DIM; kc += 64) {
        __syncthreads();
        #pragma unroll
        for (int i = 0; i < 24; i++) {
            int e = i*256 + t;
            int m = e >> 6, kk = e & 63;
            float v = A[(size_t)(m0+m)*DIM + kc + kk];
            As2f[(m >> 1)*128 + kk*2 + (m & 1)] = v;
        }
        #pragma unroll
        for (int i = 0; i < 16; i++) {
            int e = i*256 + t;
            int kk = e >> 6, c = e & 63;
            Bs[kk][c] = W[(size_t)(kc+kk)*DA + c];
        }
        __syncthreads();
        #pragma unroll
        for (int k4 = 0; k4 < 16; k4++) {
            int kk = k4*4;
            unsigned long long b2[4][4];
            #pragma unroll
            for (int jk = 0; jk < 4; jk++) {
                float4 bv = *(const float4*)&Bs[kk+jk][tx*4];
                PACK2(b2[jk][0], bv.x, bv.x);
                PACK2(b2[jk][1], bv.y, bv.y);
                PACK2(b2[jk][2], bv.z, bv.z);
                PACK2(b2[jk][3], bv.w, bv.w);
            }
            #pragma unroll
            for (int mp = 0; mp < 3; mp++) {
                const unsigned long long* arow = &As2[(ty*3+mp)*64 + kk];
                ulonglong2 a01 = *(const ulonglong2*)(arow);
                ulonglong2 a23 = *(const ulonglong2*)(arow + 2);
                #pragma unroll
                for (int j = 0; j < 4; j++) {
                    FMA2(acc2[mp][j], a01.x, b2[0][j], acc2[mp][j]);
                    FMA2(acc2[mp][j], a01.y, b2[1][j], acc2[mp][j]);
                    FMA2(acc2[mp][j], a23.x, b2[2][j], acc2[mp][j]);
                    FMA2(acc2[mp][j], a23.y, b2[3][j], acc2[mp][j]);
                }
            }
        }
    }
    float4 bv = *(const float4*)&bias[tx*4];
    float bb[4] = {bv.x, bv.y, bv.z, bv.w};
    #pragma unroll
    for (int mp = 0; mp < 3; mp++) {
        float4 lo4, hi4;
        float* lop = (float*)&lo4; float* hip = (float*)&hi4;
        #pragma unroll
        for (int j = 0; j < 4; j++) {
            float2 f = *(float2*)&acc2[mp][j];
            lop[j] = 1.f/(1.f + expf(-(f.x + bb[j])));
            hip[j] = 1.f/(1.f + expf(-(f.y + bb[j])));
        }
        int m = m0 + ty*6 + mp*2;
        *(float4*)&g_feat_ad[(size_t)m*DA + tx*4]     = lo4;   // DA=64 -> aligned
        *(float4*)&g_feat_ad[(size_t)(m+1)*DA + tx*4] = hi4;
    }
}

// ---------------- L = feat_ad @ proto_ad^T  (96x64 tile, f32x2) ----------------
__global__ __launch_bounds__(256) void l_gemm(float* __restrict__ Lout) {
    __shared__ __align__(16) unsigned long long As2[48*64];
    __shared__ float Bs[64][68];
    float* As2f = (float*)As2;
    int m0 = blockIdx.x*96, n0 = blockIdx.y*64;
    int t = threadIdx.x, tx = t & 15, ty = t >> 4;
    #pragma unroll
    for (int i = 0; i < 24; i++) {
        int e = i*256 + t;
        int m = e >> 6, kk = e & 63;
        float v = g_feat_ad[(size_t)(m0+m)*DA + kk];
        As2f[(m >> 1)*128 + kk*2 + (m & 1)] = v;
    }
    #pragma unroll
    for (int i = 0; i < 16; i++) {
        int e = i*256 + t;
        int n = e >> 6, kk = e & 63;
        Bs[kk][n] = (n0+n < CK) ? g_proto_ad[(size_t)(n0+n)*DA + kk] : 0.f;
    }
    __syncthreads();
    unsigned long long acc2[3][4];
    #pragma unroll
    for (int i = 0; i < 3; i++)
        #pragma unroll
        for (int j = 0; j < 4; j++) acc2[i][j] = 0ull;
    #pragma unroll
    for (int k4 = 0; k4 < 16; k4++) {
        int kk = k4*4;
        unsigned long long b2[4][4];
        #pragma unroll
        for (int jk = 0; jk < 4; jk++) {
            float4 bv = *(const float4*)&Bs[kk+jk][tx*4];
            PACK2(b2[jk][0], bv.x, bv.x);
            PACK2(b2[jk][1], bv.y, bv.y);
            PACK2(b2[jk][2], bv.z, bv.z);
            PACK2(b2[jk][3], bv.w, bv.w);
        }
        #pragma unroll
        for (int mp = 0; mp < 3; mp++) {
            const unsigned long long* arow = &As2[(ty*3+mp)*64 + kk];
            ulonglong2 a01 = *(const ulonglong2*)(arow);
            ulonglong2 a23 = *(const ulonglong2*)(arow + 2);
            #pragma unroll
            for (int j = 0; j < 4; j++) {
                FMA2(acc2[mp][j], a01.x, b2[0][j], acc2[mp][j]);
                FMA2(acc2[mp][j], a01.y, b2[1][j], acc2[mp][j]);
                FMA2(acc2[mp][j], a23.x, b2[2][j], acc2[mp][j]);
                FMA2(acc2[mp][j], a23.y, b2[3][j], acc2[mp][j]);
            }
        }
    }
    // scalar stores: CK=1005 is odd, row bases are NOT 16B-aligned
    #pragma unroll
    for (int mp = 0; mp < 3; mp++) {
        size_t m = (size_t)(m0 + ty*6 + mp*2);
        #pragma unroll
        for (int j = 0; j < 4; j++) {
            int n = n0 + tx*4 + j;
            float2 f = *(float2*)&acc2[mp][j];
            if (n < CK) {
                Lout[m*CK + n]     = f.x;
                Lout[(m+1)*CK + n] = f.y;
            }
        }
    }
}

// ---------------- image_logits = max over NP (L >= 0, int-bits atomicMax valid) -------
__global__ __launch_bounds__(1024) void imgmax_kernel(const float* __restrict__ L,
                                                      float* __restrict__ img) {
    int b = blockIdx.x;   // 0..15
    int j = blockIdx.y;   // 0..15 (n chunk of 81)
    int ck = threadIdx.x;
    if (ck >= CK) return;
    const float* base = L + ((size_t)b*NP + (size_t)j*81)*CK + ck;
    float m = 0.f;
    #pragma unroll 3
    for (int n = 0; n < 81; n++) m = fmaxf(m, base[(size_t)n*CK]);
    atomicMax((int*)&img[(size_t)b*CK + ck], __float_as_int(m));
}

// ---------------- class_logits ----------------
__global__ __launch_bounds__(256) void classlog_kernel(const float* __restrict__ img,
                                                       const float* __restrict__ sa,
                                                       float* __restrict__ out) {
    int b = blockIdx.x;
    int c = threadIdx.x;
    if (c >= Cc-1) return;
    float s[Kp]; float mx = -INFINITY;
    #pragma unroll
    for (int k = 0; k < Kp; k++) { s[k] = sa[c*Kp + k]; mx = fmaxf(mx, s[k]); }
    float e[Kp]; float tot = 0.f;
    #pragma unroll
    for (int k = 0; k < Kp; k++) { e[k] = expf(s[k]-mx); tot += e[k]; }
    float acc = 0.f;
    #pragma unroll
    for (int k = 0; k < Kp; k++) {
        float w = e[k]/tot*(float)Kp;
        acc += img[(size_t)b*CK + c*Kp + k]*w;
    }
    out[(size_t)b*(Cc-1) + c] = acc;
}

// ---------------- pseudo labels (fg/bg decision) + counts ----------------
__global__ __launch_bounds__(512) void pseudo_kernel(const float* __restrict__ L,
                                                     const int* __restrict__ labels,
                                                     float* __restrict__ out_pl) {
    __shared__ float fg[NP], bg[NP];
    __shared__ float red[512];
    int b = blockIdx.x, t = threadIdx.x;
    int lab = labels[b];
    for (int n = t; n < NP; n += 512) {
        const float* p = L + ((size_t)b*NP + n)*CK;
        float f = 0.f, g = 0.f;
        #pragma unroll
        for (int k = 0; k < Kp; k++) { f += p[lab*Kp + k]; g += p[(Cc-1)*Kp + k]; }
        fg[n] = f; bg[n] = g;
    }
    __syncthreads();
    float sf = 0.f, sb = 0.f;
    for (int n = t; n < NP; n += 512) { sf += fabsf(fg[n]); sb += fabsf(bg[n]); }
    red[t] = sf; __syncthreads();
    for (int off = 256; off > 0; off >>= 1) { if (t < off) red[t] += red[t+off]; __syncthreads(); }
    float Sf = fmaxf(red[0], 1e-12f); __syncthreads();
    red[t] = sb; __syncthreads();
    for (int off = 256; off > 0; off >>= 1) { if (t < off) red[t] += red[t+off]; __syncthreads(); }
    float Sb = fmaxf(red[0], 1e-12f); __syncthreads();
    for (int n = t; n < NP; n += 512) {
        bool m = (fg[n]/Sf) > (bg[n]/Sb);
        int pl = m ? lab : (Cc-1);
        out_pl[(size_t)b*NP + n] = (float)pl;
        g_labels_flat[b*NP + n] = pl;
        atomicAdd(&g_counts[pl], 1);
    }
}

// ---------------- masked sinkhorn per class (block per class) ----------------
__global__ __launch_bounds__(512) void sinkhorn_kernel(const float* __restrict__ L) {
    int c = blockIdx.x, t = threadIdx.x;
    int n_c = g_counts[c];
    if (n_c == 0) return;
    __shared__ float red[512];
    __shared__ float bc[8];

    float lm = -INFINITY;
    for (int n = t; n < Nn; n += 512) {
        if (g_labels_flat[n] == c) {
            const float* p = L + (size_t)n*CK + c*Kp;
            #pragma unroll
            for (int k = 0; k < Kp; k++) lm = fmaxf(lm, p[k]);
        }
    }
    red[t] = lm; __syncthreads();
    for (int off = 256; off > 0; off >>= 1) { if (t < off) red[t] = fmaxf(red[t], red[t+off]); __syncthreads(); }
    float lmax = red[0]; __syncthreads();

    float tot = 0.f;
    for (int n = t; n < Nn; n += 512) {
        if (g_labels_flat[n] == c) {
            const float* p = L + (size_t)n*CK + c*Kp;
            float* q = g_Qn + (size_t)n*Kp;
            #pragma unroll
            for (int k = 0; k < Kp; k++) { float e = expf((p[k]-lmax)/0.05f); q[k] = e; tot += e; }
        }
    }
    red[t] = tot; __syncthreads();
    for (int off = 256; off > 0; off >>= 1) { if (t < off) red[t] += red[t+off]; __syncthreads(); }
    float T = fmaxf(red[0], 1e-12f); __syncthreads();

    for (int n = t; n < Nn; n += 512)
        if (g_labels_flat[n] == c) {
            float* q = g_Qn + (size_t)n*Kp;
            #pragma unroll
            for (int k = 0; k < Kp; k++) q[k] = q[k]/T;
        }
    __syncthreads();

    float ncf = fmaxf((float)n_c, 1.0f);
    for (int it = 0; it < 3; it++) {
        float cs[Kp] = {0,0,0,0,0};
        for (int n = t; n < Nn; n += 512)
            if (g_labels_flat[n] == c) {
                float* q = g_Qn + (size_t)n*Kp;
                #pragma unroll
                for (int k = 0; k < Kp; k++) cs[k] += q[k];
            }
        #pragma unroll
        for (int k = 0; k < Kp; k++) {
            red[t] = cs[k]; __syncthreads();
            for (int off = 256; off > 0; off >>= 1) { if (t < off) red[t] += red[t+off]; __syncthreads(); }
            if (t == 0) bc[k] = fmaxf(red[0], 1e-12f);
            __syncthreads();
        }
        float csm[Kp];
        #pragma unroll
        for (int k = 0; k < Kp; k++) csm[k] = bc[k];
        for (int n = t; n < Nn; n += 512)
            if (g_labels_flat[n] == c) {
                float* q = g_Qn + (size_t)n*Kp;
                float qq[Kp]; float rs = 0.f;
                #pragma unroll
                for (int k = 0; k < Kp; k++) { qq[k] = q[k]/csm[k]/5.0f; rs += qq[k]; }
                rs = fmaxf(rs, 1e-12f);
                #pragma unroll
                for (int k = 0; k < Kp; k++) {
                    float v = qq[k]/rs/ncf;
                    if (it == 2) v *= ncf;
                    q[k] = v;
                }
            }
        __syncthreads();
    }
}

// ---------------- part assignment maps ----------------
__global__ __launch_bounds__(256) void part_kernel(float* __restrict__ out) {
    int n = blockIdx.x*256 + threadIdx.x;
    if (n >= Nn) return;
    const float* q = g_Qn + (size_t)n*Kp;
    int bi = 0; float best = q[0];
    #pragma unroll
    for (int k = 1; k < Kp; k++) if (q[k] > best) { best = q[k]; bi = k; }
    out[n] = (float)(bi + g_labels_flat[n]*Kp);
}

// ---------------- P_cand = sum_n Q[c,n,k] * l2norm(patch)[n,d] ----------------
__global__ __launch_bounds__(128) void pcand_kernel(const float* __restrict__ patches,
                                                    const int* __restrict__ labels) {
    int b = blockIdx.x, dc = blockIdx.y, ps = blockIdx.z, t = threadIdx.x;
    int labfg = labels[b];
    float accF[Kp] = {0,0,0,0,0};
    float accB[Kp] = {0,0,0,0,0};
    int n0 = b*NP + ps*324;
    const float* base = patches + (size_t)dc*128 + t;
    #pragma unroll 4
    for (int p = 0; p < 324; p++) {
        int n = n0 + p;
        float v = base[(size_t)n*DIM] * g_invn[n];
        int lab = g_labels_flat[n];
        const float* q = g_Qn + (size_t)n*Kp;
        if (lab == Cc-1) {
            #pragma unroll
            for (int k = 0; k < Kp; k++) accB[k] += q[k]*v;
        } else {
            #pragma unroll
            for (int k = 0; k < Kp; k++) accF[k] += q[k]*v;
        }
    }
    int d = dc*128 + t;
    #pragma unroll
    for (int k = 0; k < Kp; k++) {
        atomicAdd(&g_Pcand[((size_t)labfg*Kp + k)*DIM + d],   accF[k]);
        atomicAdd(&g_Pcand[((size_t)(Cc-1)*Kp + k)*DIM + d],  accB[k]);
    }
}

// ---------------- P_new ----------------
__global__ __launch_bounds__(256) void pnew_kernel(const float* __restrict__ proto,
                                                   float* __restrict__ out) {
    int ck = blockIdx.x, t = threadIdx.x;
    int c = ck/Kp;
    bool present = (g_counts[c] > 0);
    for (int d = t; d < DIM; d += 256) {
        size_t idx = (size_t)ck*DIM + d;
        float p = proto[idx];
        out[idx] = present ? (0.999f*p + 0.001f*g_Pcand[idx]) : p;
    }
}

// ---------------- launch ----------------
extern "C" void kernel_launch(void* const* d_in, const int* in_sizes, int n_in,
                              void* d_out, int out_size) {
    const float* patch  = (const float*)d_in[0];
    const float* proto  = (const float*)d_in[1];
    const float* sa     = (const float*)d_in[2];
    const float* wf     = (const float*)d_in[3];
    const float* bf     = (const float*)d_in[4];
    const float* wp     = (const float*)d_in[5];
    const float* bp     = (const float*)d_in[6];
    const int*   labels = (const int*)d_in[7];
    float* out  = (float*)d_out;
    float* Lout = out + OFF_L;
    float* img  = out + OFF_IMG;

    zero_kernel<<<(CK*DIM + 255)/256, 256>>>(img);
    proto_kernel<<<CK, 64>>>(proto, wp, bp);
    feat_gemm<<<Nn/96, 256>>>(patch, wf, bf);
    norm_kernel<<<(Nn*32 + 255)/256, 256>>>(patch);
    l_gemm<<<dim3(Nn/96, (CK+63)/64), 256>>>(Lout);
    imgmax_kernel<<<dim3(Bn, 16), 1024>>>(Lout, img);
    classlog_kernel<<<Bn, 256>>>(img, sa, out + OFF_CLASS);
    pseudo_kernel<<<Bn, 512>>>(Lout, labels, out + OFF_PSEUDO);
    sinkhorn_kernel<<<Cc, 512>>>(Lout);
    part_kernel<<<(Nn + 255)/256, 256>>>(out + OFF_PART);
    pcand_kernel<<<dim3(Bn, 6, 4), 128>>>(patch, labels);
    pnew_kernel<<<CK, 256>>>(proto, out + OFF_PNEW);
}